// round 2
// baseline (speedup 1.0000x reference)
#include <cuda_runtime.h>

// Problem constants
#define NB 4
#define NS 1024
#define ND 1024
#define NH 16
#define DH 64
#define NM (NB * NS)   // 4096 rows

// Scratch (allocation-free rule: __device__ globals)
__device__ float g_xn[NM * ND];          // layernormed input [4096,1024]
__device__ float g_q[NM * ND];           // q as [B*H][S][64]
__device__ float g_k[NM * ND];
__device__ float g_v[NM * ND];

// ---------------------------------------------------------------------------
// Kernel 1: LayerNorm. One block per row (4096 rows), 256 threads, float4.
// ---------------------------------------------------------------------------
__global__ void __launch_bounds__(256)
ln_kernel(const float* __restrict__ x,
          const float* __restrict__ gamma,
          const float* __restrict__ beta) {
    int row = blockIdx.x;
    int tid = threadIdx.x;
    const float4* xr = reinterpret_cast<const float4*>(x + (size_t)row * ND);
    float4 v = xr[tid];

    float s1 = v.x + v.y + v.z + v.w;
    float s2 = v.x * v.x + v.y * v.y + v.z * v.z + v.w * v.w;

    __shared__ float red1[8];
    __shared__ float red2[8];
    #pragma unroll
    for (int o = 16; o; o >>= 1) {
        s1 += __shfl_xor_sync(0xffffffffu, s1, o);
        s2 += __shfl_xor_sync(0xffffffffu, s2, o);
    }
    if ((tid & 31) == 0) { red1[tid >> 5] = s1; red2[tid >> 5] = s2; }
    __syncthreads();
    if (tid == 0) {
        float t1 = 0.f, t2 = 0.f;
        #pragma unroll
        for (int i = 0; i < 8; i++) { t1 += red1[i]; t2 += red2[i]; }
        red1[0] = t1; red2[0] = t2;
    }
    __syncthreads();
    float mu = red1[0] * (1.0f / ND);
    float var = red2[0] * (1.0f / ND) - mu * mu;
    float rstd = rsqrtf(var + 1e-5f);

    const float4 g4 = reinterpret_cast<const float4*>(gamma)[tid];
    const float4 b4 = reinterpret_cast<const float4*>(beta)[tid];
    float4 o;
    o.x = (v.x - mu) * rstd * g4.x + b4.x;
    o.y = (v.y - mu) * rstd * g4.y + b4.y;
    o.z = (v.z - mu) * rstd * g4.z + b4.z;
    o.w = (v.w - mu) * rstd * g4.w + b4.w;
    reinterpret_cast<float4*>(g_xn + (size_t)row * ND)[tid] = o;
}

// ---------------------------------------------------------------------------
// Kernel 2: QKV projection GEMM.  C[4096,1024] = xn @ W + b, z selects q/k/v.
// 128x128 block tile, BK=16, 256 threads, 8x8 register tile.
// Epilogue scatters into [B*H][S][64] layout for the attention kernel.
// ---------------------------------------------------------------------------
__global__ void __launch_bounds__(256)
qkv_gemm(const float* __restrict__ Wq, const float* __restrict__ bq,
         const float* __restrict__ Wk, const float* __restrict__ bk,
         const float* __restrict__ Wv, const float* __restrict__ bv) {
    __shared__ float As[16][128];
    __shared__ float Bs[16][128];

    int z = blockIdx.z;
    const float* W    = (z == 0) ? Wq : (z == 1) ? Wk : Wv;
    const float* bias = (z == 0) ? bq : (z == 1) ? bk : bv;
    float* outp       = (z == 0) ? g_q : (z == 1) ? g_k : g_v;

    int tid = threadIdx.x;
    int m0 = blockIdx.y << 7;
    int n0 = blockIdx.x << 7;
    int ty = tid >> 4, tx = tid & 15;

    float acc[8][8];
    #pragma unroll
    for (int i = 0; i < 8; i++)
        #pragma unroll
        for (int j = 0; j < 8; j++) acc[i][j] = 0.f;

    int ar = tid >> 2, ac = (tid & 3) << 2;   // A: 2 phases of 64 rows x 16 cols
    int br = tid >> 5, bc = (tid & 31) << 2;  // B: 2 phases of 8 rows x 128 cols

    for (int k0 = 0; k0 < ND; k0 += 16) {
        float4 a0 = *(const float4*)(g_xn + (size_t)(m0 + ar) * ND + k0 + ac);
        float4 a1 = *(const float4*)(g_xn + (size_t)(m0 + 64 + ar) * ND + k0 + ac);
        float4 b0 = *(const float4*)(W + (size_t)(k0 + br) * ND + n0 + bc);
        float4 b1 = *(const float4*)(W + (size_t)(k0 + 8 + br) * ND + n0 + bc);
        __syncthreads();
        As[ac + 0][ar] = a0.x; As[ac + 1][ar] = a0.y;
        As[ac + 2][ar] = a0.z; As[ac + 3][ar] = a0.w;
        As[ac + 0][64 + ar] = a1.x; As[ac + 1][64 + ar] = a1.y;
        As[ac + 2][64 + ar] = a1.z; As[ac + 3][64 + ar] = a1.w;
        *(float4*)&Bs[br][bc]     = b0;
        *(float4*)&Bs[br + 8][bc] = b1;
        __syncthreads();

        #pragma unroll
        for (int k = 0; k < 16; k++) {
            float a[8], b[8];
            *(float4*)(a)     = *(const float4*)&As[k][ty * 8];
            *(float4*)(a + 4) = *(const float4*)&As[k][ty * 8 + 4];
            *(float4*)(b)     = *(const float4*)&Bs[k][tx * 8];
            *(float4*)(b + 4) = *(const float4*)&Bs[k][tx * 8 + 4];
            #pragma unroll
            for (int i = 0; i < 8; i++)
                #pragma unroll
                for (int j = 0; j < 8; j++) acc[i][j] += a[i] * b[j];
        }
    }

    #pragma unroll
    for (int i = 0; i < 8; i++) {
        int row = m0 + ty * 8 + i;
        int b_ = row >> 10, s = row & 1023;
        #pragma unroll
        for (int j = 0; j < 8; j++) {
            int col = n0 + tx * 8 + j;
            int h = col >> 6, d = col & 63;
            outp[(size_t)(((b_ * NH + h) << 10) + s) * DH + d] = acc[i][j] + bias[col];
        }
    }
}

// ---------------------------------------------------------------------------
// Kernel 3: attention. grid (16 q-tiles, 64 bh). 256 threads, 4x4 microtiles.
// Writes unnormalized expS to attn region during the chunk loop, then
// re-reads (L2-hot), normalizes, and zero-fills the masked region.
// seq epilogue: x + (expS @ V) / rowsum.
// ---------------------------------------------------------------------------
__global__ void __launch_bounds__(256)
attn_kernel(const float* __restrict__ x,
            const int* __restrict__ kvlen,
            float* __restrict__ out_seq,
            float* __restrict__ out_attn) {
    extern __shared__ float sm[];
    float* Qs  = sm;                   // [64][64]
    float* KsT = sm + 64 * 64;         // [64][68]  d-major: KsT[d][j]
    float* Vs  = KsT + 64 * 68;        // [64][68]  j-major: Vs[j][dv]
    float* Ps  = Vs + 64 * 68;         // [64][68]  Ps[q][j]

    int tid = threadIdx.x;
    int bh = blockIdx.y;
    int b_ = bh >> 4, h = bh & 15;
    int q0 = blockIdx.x << 6;
    int kv = kvlen[b_];
    int ty = tid >> 4, tx = tid & 15;

    // load Q tile (rows q0..q0+63 of this bh)
    const float4* qbase = reinterpret_cast<const float4*>(g_q + (size_t)(bh * NS + q0) * DH);
    for (int i = tid; i < 64 * 64 / 4; i += 256)
        reinterpret_cast<float4*>(Qs)[i] = qbase[i];

    float acc[4][4];
    #pragma unroll
    for (int i = 0; i < 4; i++)
        #pragma unroll
        for (int j = 0; j < 4; j++) acc[i][j] = 0.f;
    float rsum[4] = {0.f, 0.f, 0.f, 0.f};

    int jend = min(q0 + 64, kv);  // valid k < jend

    for (int j0 = 0; j0 < jend; j0 += 64) {
        __syncthreads();
        // load K chunk transposed: KsT[d][j]
        const float* kbase = g_k + (size_t)(bh * NS + j0) * DH;
        for (int idx = tid; idx < 1024; idx += 256) {
            int r = idx >> 4;            // K row (j) 0..63
            int c4 = (idx & 15) << 2;    // d group
            float4 k4 = reinterpret_cast<const float4*>(kbase + (size_t)r * DH)[idx & 15];
            KsT[(c4 + 0) * 68 + r] = k4.x;
            KsT[(c4 + 1) * 68 + r] = k4.y;
            KsT[(c4 + 2) * 68 + r] = k4.z;
            KsT[(c4 + 3) * 68 + r] = k4.w;
        }
        // load V chunk: Vs[j][dv]
        const float* vbase = g_v + (size_t)(bh * NS + j0) * DH;
        for (int idx = tid; idx < 1024; idx += 256) {
            int r = idx >> 4, c = idx & 15;
            reinterpret_cast<float4*>(Vs + r * 68)[c] =
                reinterpret_cast<const float4*>(vbase + (size_t)r * DH)[c];
        }
        __syncthreads();

        // scores: p[i][jj] = Q[q0+ty4+i,:] . K[j0+tx4+jj,:]
        float p[4][4];
        #pragma unroll
        for (int i = 0; i < 4; i++)
            #pragma unroll
            for (int j = 0; j < 4; j++) p[i][j] = 0.f;

        #pragma unroll 8
        for (int d = 0; d < 64; d++) {
            float a0 = Qs[(ty * 4 + 0) * 64 + d];
            float a1 = Qs[(ty * 4 + 1) * 64 + d];
            float a2 = Qs[(ty * 4 + 2) * 64 + d];
            float a3 = Qs[(ty * 4 + 3) * 64 + d];
            float4 bv = *(const float4*)&KsT[d * 68 + tx * 4];
            p[0][0] += a0 * bv.x; p[0][1] += a0 * bv.y; p[0][2] += a0 * bv.z; p[0][3] += a0 * bv.w;
            p[1][0] += a1 * bv.x; p[1][1] += a1 * bv.y; p[1][2] += a1 * bv.z; p[1][3] += a1 * bv.w;
            p[2][0] += a2 * bv.x; p[2][1] += a2 * bv.y; p[2][2] += a2 * bv.z; p[2][3] += a2 * bv.w;
            p[3][0] += a3 * bv.x; p[3][1] += a3 * bv.y; p[3][2] += a3 * bv.z; p[3][3] += a3 * bv.w;
        }

        // mask + exp; write unnormalized to attn out; stash in Ps for PV
        #pragma unroll
        for (int i = 0; i < 4; i++) {
            int q = q0 + ty * 4 + i;
            float4 e;
            int k0i = j0 + tx * 4;
            e.x = (k0i + 0 <= q && k0i + 0 < kv) ? __expf(p[i][0] * 0.125f) : 0.f;
            e.y = (k0i + 1 <= q && k0i + 1 < kv) ? __expf(p[i][1] * 0.125f) : 0.f;
            e.z = (k0i + 2 <= q && k0i + 2 < kv) ? __expf(p[i][2] * 0.125f) : 0.f;
            e.w = (k0i + 3 <= q && k0i + 3 < kv) ? __expf(p[i][3] * 0.125f) : 0.f;
            rsum[i] += e.x + e.y + e.z + e.w;
            *(float4*)&Ps[(ty * 4 + i) * 68 + tx * 4] = e;
            *(float4*)(out_attn + (((size_t)(bh << 10 | q)) << 10) + k0i) = e;
        }
        __syncthreads();

        // O += P @ V
        #pragma unroll 8
        for (int j = 0; j < 64; j++) {
            float a0 = Ps[(ty * 4 + 0) * 68 + j];
            float a1 = Ps[(ty * 4 + 1) * 68 + j];
            float a2 = Ps[(ty * 4 + 2) * 68 + j];
            float a3 = Ps[(ty * 4 + 3) * 68 + j];
            float4 vv = *(const float4*)&Vs[j * 68 + tx * 4];
            acc[0][0] += a0 * vv.x; acc[0][1] += a0 * vv.y; acc[0][2] += a0 * vv.z; acc[0][3] += a0 * vv.w;
            acc[1][0] += a1 * vv.x; acc[1][1] += a1 * vv.y; acc[1][2] += a1 * vv.z; acc[1][3] += a1 * vv.w;
            acc[2][0] += a2 * vv.x; acc[2][1] += a2 * vv.y; acc[2][2] += a2 * vv.z; acc[2][3] += a2 * vv.w;
            acc[3][0] += a3 * vv.x; acc[3][1] += a3 * vv.y; acc[3][2] += a3 * vv.z; acc[3][3] += a3 * vv.w;
        }
    }

    // rowsum reduce across the 16 tx threads (reuse Ps)
    __syncthreads();
    #pragma unroll
    for (int i = 0; i < 4; i++) Ps[(ty * 4 + i) * 68 + tx] = rsum[i];
    __syncthreads();
    float rs[4];
    #pragma unroll
    for (int i = 0; i < 4; i++) {
        float t = 0.f;
        #pragma unroll
        for (int c = 0; c < 16; c++) t += Ps[(ty * 4 + i) * 68 + c];
        rs[i] = t;
    }

    // normalize attn rows + zero-fill masked region (full 1024 cols per row)
    #pragma unroll
    for (int i = 0; i < 4; i++) {
        int q = q0 + ty * 4 + i;
        float inv = 1.0f / rs[i];
        float* rowp = out_attn + (((size_t)(bh << 10 | q)) << 10);
        int kvq = min(q + 1, kv);   // valid k in [0, kvq)
        for (int c4 = tx * 4; c4 < 1024; c4 += 64) {
            float4 v;
            if (c4 + 4 <= kvq) {
                v = *(float4*)(rowp + c4);
                v.x *= inv; v.y *= inv; v.z *= inv; v.w *= inv;
            } else if (c4 >= kvq) {
                v = make_float4(0.f, 0.f, 0.f, 0.f);
            } else {
                v = *(float4*)(rowp + c4);
                v.x = (c4 + 0 < kvq) ? v.x * inv : 0.f;
                v.y = (c4 + 1 < kvq) ? v.y * inv : 0.f;
                v.z = (c4 + 2 < kvq) ? v.z * inv : 0.f;
                v.w = (c4 + 3 < kvq) ? v.w * inv : 0.f;
            }
            *(float4*)(rowp + c4) = v;
        }
    }

    // seq epilogue: residual + O/rowsum, scattered to (b, q, h*64+dv)
    #pragma unroll
    for (int i = 0; i < 4; i++) {
        int q = q0 + ty * 4 + i;
        float inv = 1.0f / rs[i];
        size_t off = (((size_t)(b_ << 10 | q)) << 10) + (h << 6) + tx * 4;
        float4 xv = *(const float4*)(x + off);
        float4 o;
        o.x = xv.x + acc[i][0] * inv;
        o.y = xv.y + acc[i][1] * inv;
        o.z = xv.z + acc[i][2] * inv;
        o.w = xv.w + acc[i][3] * inv;
        *(float4*)(out_seq + off) = o;
    }
}

// ---------------------------------------------------------------------------
extern "C" void kernel_launch(void* const* d_in, const int* in_sizes, int n_in,
                              void* d_out, int out_size) {
    (void)in_sizes; (void)n_in; (void)out_size;
    const float* x     = (const float*)d_in[0];
    // d_in[1], d_in[2] identical to x (self-attention)
    const int*   kvlen = (const int*)d_in[3];
    const float* gamma = (const float*)d_in[4];
    const float* beta  = (const float*)d_in[5];
    const float* Wq = (const float*)d_in[6];
    const float* bq = (const float*)d_in[7];
    const float* Wk = (const float*)d_in[8];
    const float* bk = (const float*)d_in[9];
    const float* Wv = (const float*)d_in[10];
    const float* bv = (const float*)d_in[11];

    float* out_seq  = (float*)d_out;
    float* out_attn = out_seq + (size_t)NB * NS * ND;

    ln_kernel<<<NM, 256>>>(x, gamma, beta);
    qkv_gemm<<<dim3(8, 32, 3), 256>>>(Wq, bq, Wk, bk, Wv, bv);

    const int SMEM = (64 * 64 + 3 * 64 * 68) * 4;  // 68608 bytes
    cudaFuncSetAttribute(attn_kernel,
                         cudaFuncAttributeMaxDynamicSharedMemorySize, SMEM);
    attn_kernel<<<dim3(16, 64), 256, SMEM>>>(x, kvlen, out_seq, out_attn);
}

// round 3
// speedup vs baseline: 1.3238x; 1.3238x over previous
#include <cuda_runtime.h>
#include <cstdint>

// Problem constants
#define NB 4
#define NS 1024
#define ND 1024
#define NH 16
#define DH 64
#define NM (NB * NS)   // 4096 rows

// Scratch (allocation-free rule: __device__ globals)
__device__ float g_xn[NM * ND];          // layernormed input [4096,1024]
__device__ float g_q[NM * ND];           // q as [B*H][S][64]
__device__ float g_k[NM * ND];
__device__ float g_v[NM * ND];

// ---------------------------------------------------------------------------
// helpers
// ---------------------------------------------------------------------------
__device__ __forceinline__ uint32_t f2tf32(float f) {
    uint32_t u;
    asm("cvt.rna.tf32.f32 %0, %1;" : "=r"(u) : "f"(f));
    return u;
}

__device__ __forceinline__ void mma_tf32(float c[4],
                                         uint32_t a0, uint32_t a1, uint32_t a2, uint32_t a3,
                                         uint32_t b0, uint32_t b1) {
    asm volatile(
        "mma.sync.aligned.m16n8k8.row.col.f32.tf32.tf32.f32 "
        "{%0,%1,%2,%3},{%4,%5,%6,%7},{%8,%9},{%0,%1,%2,%3};\n"
        : "+f"(c[0]), "+f"(c[1]), "+f"(c[2]), "+f"(c[3])
        : "r"(a0), "r"(a1), "r"(a2), "r"(a3), "r"(b0), "r"(b1));
}

// ---------------------------------------------------------------------------
// Kernel 1: LayerNorm. One block per row (4096 rows), 256 threads, float4.
// ---------------------------------------------------------------------------
__global__ void __launch_bounds__(256)
ln_kernel(const float* __restrict__ x,
          const float* __restrict__ gamma,
          const float* __restrict__ beta) {
    int row = blockIdx.x;
    int tid = threadIdx.x;
    const float4* xr = reinterpret_cast<const float4*>(x + (size_t)row * ND);
    float4 v = xr[tid];

    float s1 = v.x + v.y + v.z + v.w;
    float s2 = v.x * v.x + v.y * v.y + v.z * v.z + v.w * v.w;

    __shared__ float red1[8];
    __shared__ float red2[8];
    #pragma unroll
    for (int o = 16; o; o >>= 1) {
        s1 += __shfl_xor_sync(0xffffffffu, s1, o);
        s2 += __shfl_xor_sync(0xffffffffu, s2, o);
    }
    if ((tid & 31) == 0) { red1[tid >> 5] = s1; red2[tid >> 5] = s2; }
    __syncthreads();
    if (tid == 0) {
        float t1 = 0.f, t2 = 0.f;
        #pragma unroll
        for (int i = 0; i < 8; i++) { t1 += red1[i]; t2 += red2[i]; }
        red1[0] = t1; red2[0] = t2;
    }
    __syncthreads();
    float mu = red1[0] * (1.0f / ND);
    float var = red2[0] * (1.0f / ND) - mu * mu;
    float rstd = rsqrtf(var + 1e-5f);

    const float4 g4 = reinterpret_cast<const float4*>(gamma)[tid];
    const float4 b4 = reinterpret_cast<const float4*>(beta)[tid];
    float4 o;
    o.x = (v.x - mu) * rstd * g4.x + b4.x;
    o.y = (v.y - mu) * rstd * g4.y + b4.y;
    o.z = (v.z - mu) * rstd * g4.z + b4.z;
    o.w = (v.w - mu) * rstd * g4.w + b4.w;
    reinterpret_cast<float4*>(g_xn + (size_t)row * ND)[tid] = o;
}

// ---------------------------------------------------------------------------
// Kernel 2: QKV projection GEMM, tf32 tensor-core version.
// C[4096,1024] = xn @ W + b, z selects q/k/v.
// 128x128 block tile, BK=32, 256 threads (8 warps, 2x4 warp grid, each warp
// computes a 64x32 tile via 4x4 m16n8k8 mmas). Inputs rounded to tf32 at the
// smem store. Epilogue scatters into [B*H][S][64] layout.
// ---------------------------------------------------------------------------
__global__ void __launch_bounds__(256)
qkv_gemm(const float* __restrict__ Wq, const float* __restrict__ bq,
         const float* __restrict__ Wk, const float* __restrict__ bk,
         const float* __restrict__ Wv, const float* __restrict__ bv) {
    // A: [row 128][k 32], stride 36 -> fragment loads conflict-free
    // B: [k 32][col 128], stride 136 -> fragment loads conflict-free
    __shared__ float As[128][36];
    __shared__ float Bs[32][136];

    int z = blockIdx.z;
    const float* W    = (z == 0) ? Wq : (z == 1) ? Wk : Wv;
    const float* bias = (z == 0) ? bq : (z == 1) ? bk : bv;
    float* outp       = (z == 0) ? g_q : (z == 1) ? g_k : g_v;

    int tid  = threadIdx.x;
    int lane = tid & 31;
    int warp = tid >> 5;
    int wm = warp & 1;          // 0..1 -> 64-row half
    int wn = warp >> 1;         // 0..3 -> 32-col slab
    int m_base = wm * 64;
    int n_base = wn * 32;
    int qrow = lane >> 2;       // 0..7
    int qcol = lane & 3;        // 0..3

    int m0 = blockIdx.y << 7;
    int n0 = blockIdx.x << 7;

    float acc[4][4][4];
    #pragma unroll
    for (int mt = 0; mt < 4; mt++)
        #pragma unroll
        for (int nt = 0; nt < 4; nt++)
            #pragma unroll
            for (int r = 0; r < 4; r++) acc[mt][nt][r] = 0.f;

    // global-load addressing
    int a_r = tid >> 3;          // 0..31 (row within pass)
    int a_c = (tid & 7) << 2;    // 0..28 (k col)
    int b_r = tid >> 5;          // 0..7  (k row within pass)
    int b_c = (tid & 31) << 2;   // 0..124

    for (int k0 = 0; k0 < ND; k0 += 32) {
        float4 av[4], bvv[4];
        #pragma unroll
        for (int i = 0; i < 4; i++)
            av[i] = *(const float4*)(g_xn + (size_t)(m0 + a_r + 32 * i) * ND + k0 + a_c);
        #pragma unroll
        for (int i = 0; i < 4; i++)
            bvv[i] = *(const float4*)(W + (size_t)(k0 + b_r + 8 * i) * ND + n0 + b_c);

        __syncthreads();
        #pragma unroll
        for (int i = 0; i < 4; i++) {
            int r = a_r + 32 * i;
            As[r][a_c + 0] = __uint_as_float(f2tf32(av[i].x));
            As[r][a_c + 1] = __uint_as_float(f2tf32(av[i].y));
            As[r][a_c + 2] = __uint_as_float(f2tf32(av[i].z));
            As[r][a_c + 3] = __uint_as_float(f2tf32(av[i].w));
        }
        #pragma unroll
        for (int i = 0; i < 4; i++) {
            int r = b_r + 8 * i;
            Bs[r][b_c + 0] = __uint_as_float(f2tf32(bvv[i].x));
            Bs[r][b_c + 1] = __uint_as_float(f2tf32(bvv[i].y));
            Bs[r][b_c + 2] = __uint_as_float(f2tf32(bvv[i].z));
            Bs[r][b_c + 3] = __uint_as_float(f2tf32(bvv[i].w));
        }
        __syncthreads();

        #pragma unroll
        for (int ks = 0; ks < 4; ks++) {
            int kk = ks * 8;
            uint32_t af[4][4];
            #pragma unroll
            for (int mt = 0; mt < 4; mt++) {
                int r = m_base + mt * 16 + qrow;
                af[mt][0] = __float_as_uint(As[r][kk + qcol]);
                af[mt][1] = __float_as_uint(As[r + 8][kk + qcol]);
                af[mt][2] = __float_as_uint(As[r][kk + qcol + 4]);
                af[mt][3] = __float_as_uint(As[r + 8][kk + qcol + 4]);
            }
            uint32_t bf[4][2];
            #pragma unroll
            for (int nt = 0; nt < 4; nt++) {
                int c = n_base + nt * 8 + qrow;
                bf[nt][0] = __float_as_uint(Bs[kk + qcol][c]);
                bf[nt][1] = __float_as_uint(Bs[kk + qcol + 4][c]);
            }
            #pragma unroll
            for (int mt = 0; mt < 4; mt++)
                #pragma unroll
                for (int nt = 0; nt < 4; nt++)
                    mma_tf32(acc[mt][nt],
                             af[mt][0], af[mt][1], af[mt][2], af[mt][3],
                             bf[nt][0], bf[nt][1]);
        }
    }

    // epilogue: acc layout c0:(r,c) c1:(r,c+1) c2:(r+8,c) c3:(r+8,c+1)
    // with r = tilerow + qrow, c = tilecol + 2*qcol
    #pragma unroll
    for (int mt = 0; mt < 4; mt++) {
        #pragma unroll
        for (int nt = 0; nt < 4; nt++) {
            int col = n0 + n_base + nt * 8 + 2 * qcol;
            int h = col >> 6, d = col & 63;
            float bx = bias[col], by = bias[col + 1];
            #pragma unroll
            for (int half = 0; half < 2; half++) {
                int row = m0 + m_base + mt * 16 + qrow + half * 8;
                int b_ = row >> 10, s = row & 1023;
                float2 v;
                v.x = acc[mt][nt][half * 2 + 0] + bx;
                v.y = acc[mt][nt][half * 2 + 1] + by;
                *(float2*)(outp + (size_t)(((b_ * NH + h) << 10) + s) * DH + d) = v;
            }
        }
    }
}

// ---------------------------------------------------------------------------
// Kernel 3: attention. grid (16 q-tiles, 64 bh). 256 threads, 4x4 microtiles.
// Writes unnormalized expS to attn region during the chunk loop, then
// re-reads (L2-hot), normalizes, and zero-fills the masked region.
// seq epilogue: x + (expS @ V) / rowsum.
// ---------------------------------------------------------------------------
__global__ void __launch_bounds__(256)
attn_kernel(const float* __restrict__ x,
            const int* __restrict__ kvlen,
            float* __restrict__ out_seq,
            float* __restrict__ out_attn) {
    extern __shared__ float sm[];
    float* Qs  = sm;                   // [64][64]
    float* KsT = sm + 64 * 64;         // [64][68]  d-major: KsT[d][j]
    float* Vs  = KsT + 64 * 68;        // [64][68]  j-major: Vs[j][dv]
    float* Ps  = Vs + 64 * 68;         // [64][68]  Ps[q][j]

    int tid = threadIdx.x;
    int bh = blockIdx.y;
    int b_ = bh >> 4, h = bh & 15;
    int q0 = blockIdx.x << 6;
    int kv = kvlen[b_];
    int ty = tid >> 4, tx = tid & 15;

    // load Q tile (rows q0..q0+63 of this bh)
    const float4* qbase = reinterpret_cast<const float4*>(g_q + (size_t)(bh * NS + q0) * DH);
    for (int i = tid; i < 64 * 64 / 4; i += 256)
        reinterpret_cast<float4*>(Qs)[i] = qbase[i];

    float acc[4][4];
    #pragma unroll
    for (int i = 0; i < 4; i++)
        #pragma unroll
        for (int j = 0; j < 4; j++) acc[i][j] = 0.f;
    float rsum[4] = {0.f, 0.f, 0.f, 0.f};

    int jend = min(q0 + 64, kv);  // valid k < jend

    for (int j0 = 0; j0 < jend; j0 += 64) {
        __syncthreads();
        // load K chunk transposed: KsT[d][j]
        const float* kbase = g_k + (size_t)(bh * NS + j0) * DH;
        for (int idx = tid; idx < 1024; idx += 256) {
            int r = idx >> 4;            // K row (j) 0..63
            int c4 = (idx & 15) << 2;    // d group
            float4 k4 = reinterpret_cast<const float4*>(kbase + (size_t)r * DH)[idx & 15];
            KsT[(c4 + 0) * 68 + r] = k4.x;
            KsT[(c4 + 1) * 68 + r] = k4.y;
            KsT[(c4 + 2) * 68 + r] = k4.z;
            KsT[(c4 + 3) * 68 + r] = k4.w;
        }
        // load V chunk: Vs[j][dv]
        const float* vbase = g_v + (size_t)(bh * NS + j0) * DH;
        for (int idx = tid; idx < 1024; idx += 256) {
            int r = idx >> 4, c = idx & 15;
            reinterpret_cast<float4*>(Vs + r * 68)[c] =
                reinterpret_cast<const float4*>(vbase + (size_t)r * DH)[c];
        }
        __syncthreads();

        // scores: p[i][jj] = Q[q0+ty4+i,:] . K[j0+tx4+jj,:]
        float p[4][4];
        #pragma unroll
        for (int i = 0; i < 4; i++)
            #pragma unroll
            for (int j = 0; j < 4; j++) p[i][j] = 0.f;

        #pragma unroll 8
        for (int d = 0; d < 64; d++) {
            float a0 = Qs[(ty * 4 + 0) * 64 + d];
            float a1 = Qs[(ty * 4 + 1) * 64 + d];
            float a2 = Qs[(ty * 4 + 2) * 64 + d];
            float a3 = Qs[(ty * 4 + 3) * 64 + d];
            float4 bv = *(const float4*)&KsT[d * 68 + tx * 4];
            p[0][0] += a0 * bv.x; p[0][1] += a0 * bv.y; p[0][2] += a0 * bv.z; p[0][3] += a0 * bv.w;
            p[1][0] += a1 * bv.x; p[1][1] += a1 * bv.y; p[1][2] += a1 * bv.z; p[1][3] += a1 * bv.w;
            p[2][0] += a2 * bv.x; p[2][1] += a2 * bv.y; p[2][2] += a2 * bv.z; p[2][3] += a2 * bv.w;
            p[3][0] += a3 * bv.x; p[3][1] += a3 * bv.y; p[3][2] += a3 * bv.z; p[3][3] += a3 * bv.w;
        }

        // mask + exp; write unnormalized to attn out; stash in Ps for PV
        #pragma unroll
        for (int i = 0; i < 4; i++) {
            int q = q0 + ty * 4 + i;
            float4 e;
            int k0i = j0 + tx * 4;
            e.x = (k0i + 0 <= q && k0i + 0 < kv) ? __expf(p[i][0] * 0.125f) : 0.f;
            e.y = (k0i + 1 <= q && k0i + 1 < kv) ? __expf(p[i][1] * 0.125f) : 0.f;
            e.z = (k0i + 2 <= q && k0i + 2 < kv) ? __expf(p[i][2] * 0.125f) : 0.f;
            e.w = (k0i + 3 <= q && k0i + 3 < kv) ? __expf(p[i][3] * 0.125f) : 0.f;
            rsum[i] += e.x + e.y + e.z + e.w;
            *(float4*)&Ps[(ty * 4 + i) * 68 + tx * 4] = e;
            *(float4*)(out_attn + (((size_t)(bh << 10 | q)) << 10) + k0i) = e;
        }
        __syncthreads();

        // O += P @ V
        #pragma unroll 8
        for (int j = 0; j < 64; j++) {
            float a0 = Ps[(ty * 4 + 0) * 68 + j];
            float a1 = Ps[(ty * 4 + 1) * 68 + j];
            float a2 = Ps[(ty * 4 + 2) * 68 + j];
            float a3 = Ps[(ty * 4 + 3) * 68 + j];
            float4 vv = *(const float4*)&Vs[j * 68 + tx * 4];
            acc[0][0] += a0 * vv.x; acc[0][1] += a0 * vv.y; acc[0][2] += a0 * vv.z; acc[0][3] += a0 * vv.w;
            acc[1][0] += a1 * vv.x; acc[1][1] += a1 * vv.y; acc[1][2] += a1 * vv.z; acc[1][3] += a1 * vv.w;
            acc[2][0] += a2 * vv.x; acc[2][1] += a2 * vv.y; acc[2][2] += a2 * vv.z; acc[2][3] += a2 * vv.w;
            acc[3][0] += a3 * vv.x; acc[3][1] += a3 * vv.y; acc[3][2] += a3 * vv.z; acc[3][3] += a3 * vv.w;
        }
    }

    // rowsum reduce across the 16 tx threads (reuse Ps)
    __syncthreads();
    #pragma unroll
    for (int i = 0; i < 4; i++) Ps[(ty * 4 + i) * 68 + tx] = rsum[i];
    __syncthreads();
    float rs[4];
    #pragma unroll
    for (int i = 0; i < 4; i++) {
        float t = 0.f;
        #pragma unroll
        for (int c = 0; c < 16; c++) t += Ps[(ty * 4 + i) * 68 + c];
        rs[i] = t;
    }

    // normalize attn rows + zero-fill masked region (full 1024 cols per row)
    #pragma unroll
    for (int i = 0; i < 4; i++) {
        int q = q0 + ty * 4 + i;
        float inv = 1.0f / rs[i];
        float* rowp = out_attn + (((size_t)(bh << 10 | q)) << 10);
        int kvq = min(q + 1, kv);   // valid k in [0, kvq)
        for (int c4 = tx * 4; c4 < 1024; c4 += 64) {
            float4 v;
            if (c4 + 4 <= kvq) {
                v = *(float4*)(rowp + c4);
                v.x *= inv; v.y *= inv; v.z *= inv; v.w *= inv;
            } else if (c4 >= kvq) {
                v = make_float4(0.f, 0.f, 0.f, 0.f);
            } else {
                v = *(float4*)(rowp + c4);
                v.x = (c4 + 0 < kvq) ? v.x * inv : 0.f;
                v.y = (c4 + 1 < kvq) ? v.y * inv : 0.f;
                v.z = (c4 + 2 < kvq) ? v.z * inv : 0.f;
                v.w = (c4 + 3 < kvq) ? v.w * inv : 0.f;
            }
            *(float4*)(rowp + c4) = v;
        }
    }

    // seq epilogue: residual + O/rowsum, scattered to (b, q, h*64+dv)
    #pragma unroll
    for (int i = 0; i < 4; i++) {
        int q = q0 + ty * 4 + i;
        float inv = 1.0f / rs[i];
        size_t off = (((size_t)(b_ << 10 | q)) << 10) + (h << 6) + tx * 4;
        float4 xv = *(const float4*)(x + off);
        float4 o;
        o.x = xv.x + acc[i][0] * inv;
        o.y = xv.y + acc[i][1] * inv;
        o.z = xv.z + acc[i][2] * inv;
        o.w = xv.w + acc[i][3] * inv;
        *(float4*)(out_seq + off) = o;
    }
}

// ---------------------------------------------------------------------------
extern "C" void kernel_launch(void* const* d_in, const int* in_sizes, int n_in,
                              void* d_out, int out_size) {
    (void)in_sizes; (void)n_in; (void)out_size;
    const float* x     = (const float*)d_in[0];
    // d_in[1], d_in[2] identical to x (self-attention)
    const int*   kvlen = (const int*)d_in[3];
    const float* gamma = (const float*)d_in[4];
    const float* beta  = (const float*)d_in[5];
    const float* Wq = (const float*)d_in[6];
    const float* bq = (const float*)d_in[7];
    const float* Wk = (const float*)d_in[8];
    const float* bk = (const float*)d_in[9];
    const float* Wv = (const float*)d_in[10];
    const float* bv = (const float*)d_in[11];

    float* out_seq  = (float*)d_out;
    float* out_attn = out_seq + (size_t)NB * NS * ND;

    ln_kernel<<<NM, 256>>>(x, gamma, beta);
    qkv_gemm<<<dim3(8, 32, 3), 256>>>(Wq, bq, Wk, bk, Wv, bv);

    const int SMEM = (64 * 64 + 3 * 64 * 68) * 4;  // 68608 bytes
    cudaFuncSetAttribute(attn_kernel,
                         cudaFuncAttributeMaxDynamicSharedMemorySize, SMEM);
    attn_kernel<<<dim3(16, 64), 256, SMEM>>>(x, kvlen, out_seq, out_attn);
}

// round 4
// speedup vs baseline: 2.3977x; 1.8112x over previous
#include <cuda_runtime.h>
#include <cstdint>

// Problem constants
#define NB 4
#define NS 1024
#define ND 1024
#define NH 16
#define DH 64
#define NM (NB * NS)   // 4096 rows

// Scratch (allocation-free rule: __device__ globals)
__device__ float g_xn[NM * ND];          // layernormed input [4096,1024]
__device__ float g_q[NM * ND];           // q as [B*H][S][64]
__device__ float g_k[NM * ND];
__device__ float g_v[NM * ND];

// ---------------------------------------------------------------------------
// helpers
// ---------------------------------------------------------------------------
__device__ __forceinline__ uint32_t f2tf32(float f) {
    uint32_t u;
    asm("cvt.rna.tf32.f32 %0, %1;" : "=r"(u) : "f"(f));
    return u;
}
__device__ __forceinline__ float tf32rf(float f) {
    return __uint_as_float(f2tf32(f));
}

__device__ __forceinline__ void mma_tf32(float c[4],
                                         uint32_t a0, uint32_t a1, uint32_t a2, uint32_t a3,
                                         uint32_t b0, uint32_t b1) {
    asm volatile(
        "mma.sync.aligned.m16n8k8.row.col.f32.tf32.tf32.f32 "
        "{%0,%1,%2,%3},{%4,%5,%6,%7},{%8,%9},{%0,%1,%2,%3};\n"
        : "+f"(c[0]), "+f"(c[1]), "+f"(c[2]), "+f"(c[3])
        : "r"(a0), "r"(a1), "r"(a2), "r"(a3), "r"(b0), "r"(b1));
}

// ---------------------------------------------------------------------------
// Kernel 1: LayerNorm. One block per row (4096 rows), 256 threads, float4.
// ---------------------------------------------------------------------------
__global__ void __launch_bounds__(256)
ln_kernel(const float* __restrict__ x,
          const float* __restrict__ gamma,
          const float* __restrict__ beta) {
    int row = blockIdx.x;
    int tid = threadIdx.x;
    const float4* xr = reinterpret_cast<const float4*>(x + (size_t)row * ND);
    float4 v = xr[tid];

    float s1 = v.x + v.y + v.z + v.w;
    float s2 = v.x * v.x + v.y * v.y + v.z * v.z + v.w * v.w;

    __shared__ float red1[8];
    __shared__ float red2[8];
    #pragma unroll
    for (int o = 16; o; o >>= 1) {
        s1 += __shfl_xor_sync(0xffffffffu, s1, o);
        s2 += __shfl_xor_sync(0xffffffffu, s2, o);
    }
    if ((tid & 31) == 0) { red1[tid >> 5] = s1; red2[tid >> 5] = s2; }
    __syncthreads();
    if (tid == 0) {
        float t1 = 0.f, t2 = 0.f;
        #pragma unroll
        for (int i = 0; i < 8; i++) { t1 += red1[i]; t2 += red2[i]; }
        red1[0] = t1; red2[0] = t2;
    }
    __syncthreads();
    float mu = red1[0] * (1.0f / ND);
    float var = red2[0] * (1.0f / ND) - mu * mu;
    float rstd = rsqrtf(var + 1e-5f);

    const float4 g4 = reinterpret_cast<const float4*>(gamma)[tid];
    const float4 b4 = reinterpret_cast<const float4*>(beta)[tid];
    float4 o;
    o.x = (v.x - mu) * rstd * g4.x + b4.x;
    o.y = (v.y - mu) * rstd * g4.y + b4.y;
    o.z = (v.z - mu) * rstd * g4.z + b4.z;
    o.w = (v.w - mu) * rstd * g4.w + b4.w;
    reinterpret_cast<float4*>(g_xn + (size_t)row * ND)[tid] = o;
}

// ---------------------------------------------------------------------------
// Kernel 2: QKV projection GEMM, tf32 tensor-core version (unchanged R3).
// ---------------------------------------------------------------------------
__global__ void __launch_bounds__(256)
qkv_gemm(const float* __restrict__ Wq, const float* __restrict__ bq,
         const float* __restrict__ Wk, const float* __restrict__ bk,
         const float* __restrict__ Wv, const float* __restrict__ bv) {
    __shared__ float As[128][36];
    __shared__ float Bs[32][136];

    int z = blockIdx.z;
    const float* W    = (z == 0) ? Wq : (z == 1) ? Wk : Wv;
    const float* bias = (z == 0) ? bq : (z == 1) ? bk : bv;
    float* outp       = (z == 0) ? g_q : (z == 1) ? g_k : g_v;

    int tid  = threadIdx.x;
    int lane = tid & 31;
    int warp = tid >> 5;
    int wm = warp & 1;
    int wn = warp >> 1;
    int m_base = wm * 64;
    int n_base = wn * 32;
    int qrow = lane >> 2;
    int qcol = lane & 3;

    int m0 = blockIdx.y << 7;
    int n0 = blockIdx.x << 7;

    float acc[4][4][4];
    #pragma unroll
    for (int mt = 0; mt < 4; mt++)
        #pragma unroll
        for (int nt = 0; nt < 4; nt++)
            #pragma unroll
            for (int r = 0; r < 4; r++) acc[mt][nt][r] = 0.f;

    int a_r = tid >> 3;
    int a_c = (tid & 7) << 2;
    int b_r = tid >> 5;
    int b_c = (tid & 31) << 2;

    for (int k0 = 0; k0 < ND; k0 += 32) {
        float4 av[4], bvv[4];
        #pragma unroll
        for (int i = 0; i < 4; i++)
            av[i] = *(const float4*)(g_xn + (size_t)(m0 + a_r + 32 * i) * ND + k0 + a_c);
        #pragma unroll
        for (int i = 0; i < 4; i++)
            bvv[i] = *(const float4*)(W + (size_t)(k0 + b_r + 8 * i) * ND + n0 + b_c);

        __syncthreads();
        #pragma unroll
        for (int i = 0; i < 4; i++) {
            int r = a_r + 32 * i;
            As[r][a_c + 0] = tf32rf(av[i].x);
            As[r][a_c + 1] = tf32rf(av[i].y);
            As[r][a_c + 2] = tf32rf(av[i].z);
            As[r][a_c + 3] = tf32rf(av[i].w);
        }
        #pragma unroll
        for (int i = 0; i < 4; i++) {
            int r = b_r + 8 * i;
            Bs[r][b_c + 0] = tf32rf(bvv[i].x);
            Bs[r][b_c + 1] = tf32rf(bvv[i].y);
            Bs[r][b_c + 2] = tf32rf(bvv[i].z);
            Bs[r][b_c + 3] = tf32rf(bvv[i].w);
        }
        __syncthreads();

        #pragma unroll
        for (int ks = 0; ks < 4; ks++) {
            int kk = ks * 8;
            uint32_t af[4][4];
            #pragma unroll
            for (int mt = 0; mt < 4; mt++) {
                int r = m_base + mt * 16 + qrow;
                af[mt][0] = __float_as_uint(As[r][kk + qcol]);
                af[mt][1] = __float_as_uint(As[r + 8][kk + qcol]);
                af[mt][2] = __float_as_uint(As[r][kk + qcol + 4]);
                af[mt][3] = __float_as_uint(As[r + 8][kk + qcol + 4]);
            }
            uint32_t bf[4][2];
            #pragma unroll
            for (int nt = 0; nt < 4; nt++) {
                int c = n_base + nt * 8 + qrow;
                bf[nt][0] = __float_as_uint(Bs[kk + qcol][c]);
                bf[nt][1] = __float_as_uint(Bs[kk + qcol + 4][c]);
            }
            #pragma unroll
            for (int mt = 0; mt < 4; mt++)
                #pragma unroll
                for (int nt = 0; nt < 4; nt++)
                    mma_tf32(acc[mt][nt],
                             af[mt][0], af[mt][1], af[mt][2], af[mt][3],
                             bf[nt][0], bf[nt][1]);
        }
    }

    #pragma unroll
    for (int mt = 0; mt < 4; mt++) {
        #pragma unroll
        for (int nt = 0; nt < 4; nt++) {
            int col = n0 + n_base + nt * 8 + 2 * qcol;
            int h = col >> 6, d = col & 63;
            float bx = bias[col], by = bias[col + 1];
            #pragma unroll
            for (int half = 0; half < 2; half++) {
                int row = m0 + m_base + mt * 16 + qrow + half * 8;
                int b_ = row >> 10, s = row & 1023;
                float2 v;
                v.x = acc[mt][nt][half * 2 + 0] + bx;
                v.y = acc[mt][nt][half * 2 + 1] + by;
                *(float2*)(outp + (size_t)(((b_ * NH + h) << 10) + s) * DH + d) = v;
            }
        }
    }
}

// ---------------------------------------------------------------------------
// Kernel 3: attention, tf32 tensor-core version.
// grid (16 q-tiles, 64 bh), 256 threads = 8 warps.
// Warp w owns rows [(w>>1)*16, +16) x cols [(w&1)*32, +32) of each 64x64 tile.
// Per 64-k chunk: S = Q K^T via mma -> mask+exp on fragments -> Ps (smem,
// tf32-rounded) -> rowsum reduce + unnormalized global write -> O += P V via
// mma. Then normalize pass over attn rows + fragment epilogue for out_seq.
// ---------------------------------------------------------------------------
#define ATTN_SMEM ((64 * 68 * 2 + 64 * 72 * 2 + 64) * 4)

__global__ void __launch_bounds__(256)
attn_kernel(const float* __restrict__ x,
            const int* __restrict__ kvlen,
            float* __restrict__ out_seq,
            float* __restrict__ out_attn) {
    extern __shared__ float sm[];
    float* Qs    = sm;                  // [64][68] tf32, A-operand
    float* Ps    = Qs + 64 * 68;        // [64][68] tf32 exp vals, A-operand
    float* KsT   = Ps + 64 * 68;        // [64][72] tf32, [d][j], B-operand
    float* Vs    = KsT + 64 * 72;       // [64][72] tf32, [j][dv], B-operand
    float* rsums = Vs + 64 * 72;        // [64]

    int tid  = threadIdx.x;
    int lane = tid & 31;
    int warp = tid >> 5;
    int m_base = (warp >> 1) << 4;      // 0,16,32,48
    int n_base = (warp & 1) << 5;       // 0,32
    int qrow = lane >> 2;               // 0..7
    int qcol = lane & 3;                // 0..3

    int bh = blockIdx.y;
    int b_ = bh >> 4, h = bh & 15;
    int q0 = blockIdx.x << 6;
    int kv = kvlen[b_];

    // load Q tile (tf32-rounded)
    const float4* qbase = reinterpret_cast<const float4*>(g_q + (size_t)(bh * NS + q0) * DH);
    for (int i = tid; i < 1024; i += 256) {
        float4 q4 = qbase[i];
        int r = i >> 4, c = (i & 15) << 2;
        Qs[r * 68 + c + 0] = tf32rf(q4.x);
        Qs[r * 68 + c + 1] = tf32rf(q4.y);
        Qs[r * 68 + c + 2] = tf32rf(q4.z);
        Qs[r * 68 + c + 3] = tf32rf(q4.w);
    }
    if (tid < 64) rsums[tid] = 0.f;

    float acc_o[4][4];
    #pragma unroll
    for (int nt = 0; nt < 4; nt++)
        #pragma unroll
        for (int r = 0; r < 4; r++) acc_o[nt][r] = 0.f;

    int qg0 = q0 + m_base + qrow;
    int qg1 = qg0 + 8;

    int jend = min(q0 + 64, kv);

    for (int j0 = 0; j0 < jend; j0 += 64) {
        __syncthreads();   // protects Ps/KsT/Vs reuse from previous iteration

        // K chunk -> KsT[d][j] (tf32)
        const float* kbase = g_k + (size_t)(bh * NS + j0) * DH;
        for (int idx = tid; idx < 1024; idx += 256) {
            int r = idx >> 4;
            int c4 = (idx & 15) << 2;
            float4 k4 = reinterpret_cast<const float4*>(kbase + (size_t)r * DH)[idx & 15];
            KsT[(c4 + 0) * 72 + r] = tf32rf(k4.x);
            KsT[(c4 + 1) * 72 + r] = tf32rf(k4.y);
            KsT[(c4 + 2) * 72 + r] = tf32rf(k4.z);
            KsT[(c4 + 3) * 72 + r] = tf32rf(k4.w);
        }
        // V chunk -> Vs[j][dv] (tf32)
        const float* vbase = g_v + (size_t)(bh * NS + j0) * DH;
        for (int idx = tid; idx < 1024; idx += 256) {
            int r = idx >> 4, c = idx & 15;
            float4 v4 = reinterpret_cast<const float4*>(vbase + (size_t)r * DH)[c];
            float4 t;
            t.x = tf32rf(v4.x); t.y = tf32rf(v4.y);
            t.z = tf32rf(v4.z); t.w = tf32rf(v4.w);
            *(float4*)&Vs[r * 72 + (c << 2)] = t;
        }
        __syncthreads();

        // S = Q K^T (each warp: m16 x n32)
        float acc_s[4][4];
        #pragma unroll
        for (int nt = 0; nt < 4; nt++)
            #pragma unroll
            for (int r = 0; r < 4; r++) acc_s[nt][r] = 0.f;

        #pragma unroll
        for (int ks = 0; ks < 8; ks++) {
            int kk = ks * 8;
            uint32_t a0 = __float_as_uint(Qs[(m_base + qrow) * 68 + kk + qcol]);
            uint32_t a1 = __float_as_uint(Qs[(m_base + qrow + 8) * 68 + kk + qcol]);
            uint32_t a2 = __float_as_uint(Qs[(m_base + qrow) * 68 + kk + qcol + 4]);
            uint32_t a3 = __float_as_uint(Qs[(m_base + qrow + 8) * 68 + kk + qcol + 4]);
            #pragma unroll
            for (int nt = 0; nt < 4; nt++) {
                int n = n_base + nt * 8 + qrow;
                uint32_t b0 = __float_as_uint(KsT[(kk + qcol) * 72 + n]);
                uint32_t b1 = __float_as_uint(KsT[(kk + qcol + 4) * 72 + n]);
                mma_tf32(acc_s[nt], a0, a1, a2, a3, b0, b1);
            }
        }

        // mask + exp on fragments; store tf32-rounded into Ps
        #pragma unroll
        for (int nt = 0; nt < 4; nt++) {
            int kl = n_base + nt * 8 + 2 * qcol;
            int kg = j0 + kl;
            float e0 = (kg     <= qg0 && kg     < kv) ? __expf(acc_s[nt][0] * 0.125f) : 0.f;
            float e1 = (kg + 1 <= qg0 && kg + 1 < kv) ? __expf(acc_s[nt][1] * 0.125f) : 0.f;
            float e2 = (kg     <= qg1 && kg     < kv) ? __expf(acc_s[nt][2] * 0.125f) : 0.f;
            float e3 = (kg + 1 <= qg1 && kg + 1 < kv) ? __expf(acc_s[nt][3] * 0.125f) : 0.f;
            e0 = tf32rf(e0); e1 = tf32rf(e1); e2 = tf32rf(e2); e3 = tf32rf(e3);
            *(float2*)&Ps[(m_base + qrow) * 68 + kl]     = make_float2(e0, e1);
            *(float2*)&Ps[(m_base + qrow + 8) * 68 + kl] = make_float2(e2, e3);
        }
        __syncthreads();

        // rowsum reduce + unnormalized global write (from Ps)
        {
            int row = tid >> 2, part = tid & 3;
            const float* pr = Ps + row * 68 + part * 16;
            float4 p0 = *(const float4*)(pr + 0);
            float4 p1 = *(const float4*)(pr + 4);
            float4 p2 = *(const float4*)(pr + 8);
            float4 p3 = *(const float4*)(pr + 12);
            float s = p0.x + p0.y + p0.z + p0.w + p1.x + p1.y + p1.z + p1.w
                    + p2.x + p2.y + p2.z + p2.w + p3.x + p3.y + p3.z + p3.w;
            s += __shfl_xor_sync(0xffffffffu, s, 1);
            s += __shfl_xor_sync(0xffffffffu, s, 2);
            if (part == 0) rsums[row] += s;
            float* gp = out_attn + (((size_t)(bh << 10 | (q0 + row))) << 10) + j0 + part * 16;
            *(float4*)(gp + 0)  = p0;
            *(float4*)(gp + 4)  = p1;
            *(float4*)(gp + 8)  = p2;
            *(float4*)(gp + 12) = p3;
        }

        // O += P @ V
        #pragma unroll
        for (int ks = 0; ks < 8; ks++) {
            int kk = ks * 8;
            uint32_t a0 = __float_as_uint(Ps[(m_base + qrow) * 68 + kk + qcol]);
            uint32_t a1 = __float_as_uint(Ps[(m_base + qrow + 8) * 68 + kk + qcol]);
            uint32_t a2 = __float_as_uint(Ps[(m_base + qrow) * 68 + kk + qcol + 4]);
            uint32_t a3 = __float_as_uint(Ps[(m_base + qrow + 8) * 68 + kk + qcol + 4]);
            #pragma unroll
            for (int nt = 0; nt < 4; nt++) {
                int n = n_base + nt * 8 + qrow;
                uint32_t b0 = __float_as_uint(Vs[(kk + qcol) * 72 + n]);
                uint32_t b1 = __float_as_uint(Vs[(kk + qcol + 4) * 72 + n]);
                mma_tf32(acc_o[nt], a0, a1, a2, a3, b0, b1);
            }
        }
    }
    __syncthreads();

    // normalize attn rows + zero-fill masked region (full 1024 cols per row)
    {
        int ty = tid >> 4, tx = tid & 15;
        #pragma unroll
        for (int i = 0; i < 4; i++) {
            int rloc = ty * 4 + i;
            int q = q0 + rloc;
            float inv = 1.0f / rsums[rloc];
            float* rowp = out_attn + (((size_t)(bh << 10 | q)) << 10);
            int kvq = min(q + 1, kv);   // valid k in [0, kvq)
            for (int c4 = tx * 4; c4 < 1024; c4 += 64) {
                float4 v;
                if (c4 + 4 <= kvq) {
                    v = *(float4*)(rowp + c4);
                    v.x *= inv; v.y *= inv; v.z *= inv; v.w *= inv;
                } else if (c4 >= kvq) {
                    v = make_float4(0.f, 0.f, 0.f, 0.f);
                } else {
                    v = *(float4*)(rowp + c4);
                    v.x = (c4 + 0 < kvq) ? v.x * inv : 0.f;
                    v.y = (c4 + 1 < kvq) ? v.y * inv : 0.f;
                    v.z = (c4 + 2 < kvq) ? v.z * inv : 0.f;
                    v.w = (c4 + 3 < kvq) ? v.w * inv : 0.f;
                }
                *(float4*)(rowp + c4) = v;
            }
        }
    }

    // out_seq epilogue from fragments: x + O/rowsum
    {
        float inv0 = 1.0f / rsums[m_base + qrow];
        float inv1 = 1.0f / rsums[m_base + qrow + 8];
        #pragma unroll
        for (int nt = 0; nt < 4; nt++) {
            int dv = n_base + nt * 8 + 2 * qcol;
            size_t off0 = (((size_t)(b_ << 10 | qg0)) << 10) + (h << 6) + dv;
            size_t off1 = (((size_t)(b_ << 10 | qg1)) << 10) + (h << 6) + dv;
            float2 x0 = *(const float2*)(x + off0);
            float2 x1 = *(const float2*)(x + off1);
            float2 o0, o1;
            o0.x = x0.x + acc_o[nt][0] * inv0;
            o0.y = x0.y + acc_o[nt][1] * inv0;
            o1.x = x1.x + acc_o[nt][2] * inv1;
            o1.y = x1.y + acc_o[nt][3] * inv1;
            *(float2*)(out_seq + off0) = o0;
            *(float2*)(out_seq + off1) = o1;
        }
    }
}

// ---------------------------------------------------------------------------
extern "C" void kernel_launch(void* const* d_in, const int* in_sizes, int n_in,
                              void* d_out, int out_size) {
    (void)in_sizes; (void)n_in; (void)out_size;
    const float* x     = (const float*)d_in[0];
    const int*   kvlen = (const int*)d_in[3];
    const float* gamma = (const float*)d_in[4];
    const float* beta  = (const float*)d_in[5];
    const float* Wq = (const float*)d_in[6];
    const float* bq = (const float*)d_in[7];
    const float* Wk = (const float*)d_in[8];
    const float* bk = (const float*)d_in[9];
    const float* Wv = (const float*)d_in[10];
    const float* bv = (const float*)d_in[11];

    float* out_seq  = (float*)d_out;
    float* out_attn = out_seq + (size_t)NB * NS * ND;

    ln_kernel<<<NM, 256>>>(x, gamma, beta);
    qkv_gemm<<<dim3(8, 32, 3), 256>>>(Wq, bq, Wk, bk, Wv, bv);

    cudaFuncSetAttribute(attn_kernel,
                         cudaFuncAttributeMaxDynamicSharedMemorySize, ATTN_SMEM);
    attn_kernel<<<dim3(16, 64), 256, ATTN_SMEM>>>(x, kvlen, out_seq, out_attn);
}